// round 13
// baseline (speedup 1.0000x reference)
#include <cuda_runtime.h>
#include <cuda_fp16.h>
#include <cstdint>

// Problem constants (B=32, H=W=56, C=384, heads=12, ws=7, shift=3)
#define HEADS   12
#define WS      7
#define NTOK    49
#define NWIN    2048
#define M_TOTAL (NWIN * NTOK)   // 100352
#define N_QKV   1152
#define N_PROJ  384
#define KDIM    384

// fp16 GEMM tiling: CTA 64(M) x 128(N), 256 threads (8 warps, warp tile 32x32),
// BK=32 halfs (12 K-steps), 4-stage cp.async ring, ldmatrix fragment loads.
// 32 accums/thread -> ~75 regs -> 3 CTAs/SM (24 warps, 37.5% occ).
#define BM 64
#define BN 128
#define BK 32
#define KSTEPS (KDIM / BK)        // 12
#define ROW_HALF 40               // halfs per smem row (32 used + 8 pad) = 80B
#define OPA_BYTES (BM * ROW_HALF * 2)     // 5120 B  (A per stage)
#define OPB_BYTES (BN * ROW_HALF * 2)     // 10240 B (B per stage)
#define STAGE_BYTES (OPA_BYTES + OPB_BYTES)   // 15360
#define SMEM_BYTES (4 * STAGE_BYTES)          // 61440

// Scratch. g_qkv holds qkv output in HEAD-MAJOR slabs [tensor*12+head][m][32].
__device__ __half g_qkv[(size_t)M_TOTAL * N_QKV];
__device__ __half g_attn[(size_t)M_TOTAL * N_PROJ];
__device__ __half g_xh [(size_t)M_TOTAL * KDIM];
__device__ __half g_wtq[(size_t)N_QKV * KDIM];
__device__ __half g_wtp[(size_t)N_PROJ * KDIM];

// ---------------------------------------------------------------------------
__device__ __forceinline__ int win_src_index(int m) {
    int win = m / NTOK, t = m - win * NTOK;
    int b  = win >> 6, wi = win & 63;
    int wh = wi >> 3,  ww = wi & 7;
    int r  = t / WS,   c  = t - r * WS;
    int row = wh * WS + r + 3; if (row >= 56) row -= 56;
    int col = ww * WS + c + 3; if (col >= 56) col -= 56;
    return b * 3136 + row * 56 + col;
}

__device__ __forceinline__ uint32_t smem_u32(const void* p) {
    uint32_t a;
    asm("{ .reg .u64 t; cvta.to.shared.u64 t, %1; cvt.u32.u64 %0, t; }" : "=r"(a) : "l"(p));
    return a;
}

#define CP16(dst, src) \
    asm volatile("cp.async.cg.shared.global [%0], [%1], 16;" :: "r"(dst), "l"(src) : "memory")
#define CP_COMMIT() asm volatile("cp.async.commit_group;" ::: "memory")
#define CP_WAIT2()  asm volatile("cp.async.wait_group 2;" ::: "memory")
#define CP_WAIT1()  asm volatile("cp.async.wait_group 1;" ::: "memory")
#define CP_WAIT0()  asm volatile("cp.async.wait_group 0;" ::: "memory")

#define MMA_F16(c, a0, a1, a2, a3, b0, b1) \
    asm volatile("mma.sync.aligned.m16n8k16.row.col.f32.f16.f16.f32 " \
        "{%0,%1,%2,%3}, {%4,%5,%6,%7}, {%8,%9}, {%0,%1,%2,%3};" \
        : "+f"((c)[0]), "+f"((c)[1]), "+f"((c)[2]), "+f"((c)[3]) \
        : "r"(a0), "r"(a1), "r"(a2), "r"(a3), "r"(b0), "r"(b1))

#define LDSM_X4(r0, r1, r2, r3, addr) \
    asm volatile("ldmatrix.sync.aligned.m8n8.x4.shared.b16 {%0,%1,%2,%3}, [%4];" \
        : "=r"(r0), "=r"(r1), "=r"(r2), "=r"(r3) : "r"(addr))

// ---------------------------------------------------------------------------
// fp16 mma.sync GEMM (fp32 accum), ldmatrix fragment loads, 3 CTAs/SM.
// GATHER: fuse roll/window map into A rows. HEADOUT: [ncol/32][m][32] slab
// output (qkv). SCATTER: fuse inverse roll/window into output rows (proj).
template <int N_TOTAL, bool GATHER, bool SCATTER, bool HEADOUT, typename CT>
__global__ void __launch_bounds__(256, 3)
gemm_h(const __half* __restrict__ A, const __half* __restrict__ WT,
       const float* __restrict__ bias, CT* __restrict__ C)
{
    extern __shared__ __half smh[];
    const uint32_t smb = smem_u32(smh);

    const int tid  = threadIdx.x;
    const int wid  = tid >> 5, lane = tid & 31;
    const int t    = lane & 3;
    const int wm   = wid & 1, wn = wid >> 1;     // warp grid 2(M) x 4(N)
    const int m0   = blockIdx.y * BM, n0 = blockIdx.x * BN;

    // B loads: all 256 threads, 2 per row (128 rows x 32B halves)
    const int brow_i = tid >> 1, bseg = (tid & 1) * 16;
    const __half* brow = WT + (size_t)(n0 + brow_i) * KDIM + bseg;
    const uint32_t b_dst = smb + OPA_BYTES + (uint32_t)brow_i * (ROW_HALF * 2) + bseg * 2;

    // A loads: threads 0..127, 2 per row (64 rows)
    const int arow_i = (tid < 128) ? (tid >> 1) : 0;
    const int aseg   = (tid & 1) * 16;
    const __half* arow = A + (size_t)(GATHER ? win_src_index(m0 + arow_i) : (m0 + arow_i)) * KDIM + aseg;
    const uint32_t a_dst = smb + (uint32_t)arow_i * (ROW_HALF * 2) + aseg * 2;

    auto load_stage = [&](int s, int kt) {
        const uint32_t so = (uint32_t)s * STAGE_BYTES;
        const __half* bp = brow + kt * BK;
        CP16(b_dst + so,      bp);
        CP16(b_dst + so + 16, bp + 8);
        if (tid < 128) {
            const __half* ap = arow + kt * BK;
            CP16(a_dst + so,      ap);
            CP16(a_dst + so + 16, ap + 8);
        }
    };

    // ldmatrix lane addressing (x4 = four 8x8 b16 tiles)
    const int l7  = lane & 7;
    const int l8  = (lane >> 3) & 1;
    const int l16 = (lane >> 4) & 1;
    uint32_t a_addr[2];
#pragma unroll
    for (int it = 0; it < 2; it++)
        a_addr[it] = smb + (uint32_t)(((wm * 32 + it * 16 + l7 + l8 * 8) * ROW_HALF + l16 * 8) * 2);
    uint32_t b_addr[2];
#pragma unroll
    for (int jp = 0; jp < 2; jp++)
        b_addr[jp] = smb + OPA_BYTES
                   + (uint32_t)(((wn * 32 + jp * 16 + l16 * 8 + l7) * ROW_HALF + l8 * 8) * 2);

    float c[2][4][4];
#pragma unroll
    for (int i = 0; i < 2; i++)
#pragma unroll
        for (int j = 0; j < 4; j++)
#pragma unroll
            for (int q = 0; q < 4; q++) c[i][j][q] = 0.f;

#pragma unroll
    for (int s = 0; s < 3; s++) { load_stage(s, s); CP_COMMIT(); }

#pragma unroll 4
    for (int kt = 0; kt < KSTEPS; kt++) {
        const int rem = KSTEPS - 1 - kt;
        if (rem >= 2)      CP_WAIT2();
        else if (rem == 1) CP_WAIT1();
        else               CP_WAIT0();
        __syncthreads();

        if (kt + 3 < KSTEPS) { load_stage((kt + 3) & 3, kt + 3); CP_COMMIT(); }

        const uint32_t soff = (uint32_t)(kt & 3) * STAGE_BYTES;

#pragma unroll
        for (int ks = 0; ks < 2; ks++) {          // two k16 sub-steps per BK=32
            const uint32_t ko = soff + ks * 32;   // 16 halfs = 32 bytes
            uint32_t a[2][4];
#pragma unroll
            for (int it = 0; it < 2; it++)
                LDSM_X4(a[it][0], a[it][1], a[it][2], a[it][3], a_addr[it] + ko);
            uint32_t b[2][4];
#pragma unroll
            for (int jp = 0; jp < 2; jp++)
                LDSM_X4(b[jp][0], b[jp][1], b[jp][2], b[jp][3], b_addr[jp] + ko);
#pragma unroll
            for (int it = 0; it < 2; it++)
#pragma unroll
                for (int jt = 0; jt < 4; jt++)
                    MMA_F16(c[it][jt], a[it][0], a[it][1], a[it][2], a[it][3],
                            b[jt >> 1][2 * (jt & 1)], b[jt >> 1][2 * (jt & 1) + 1]);
        }
    }

    // epilogue: fp32 bias add; each 4-lane group stores 32B contiguous
    const int g = lane >> 2;
    const int ncolb = n0 + wn * 32;
    float2 bj[4];
#pragma unroll
    for (int j = 0; j < 4; j++)
        bj[j] = *reinterpret_cast<const float2*>(&bias[ncolb + j * 8 + 2 * t]);

#pragma unroll
    for (int i = 0; i < 2; i++) {
        const int mrow = m0 + wm * 32 + i * 16 + g;
        CT *p0, *p1;
        if (HEADOUT) {
            const size_t slab = (size_t)(ncolb >> 5) * M_TOTAL;
            p0 = C + (slab + mrow)     * 32 + 2 * t;
            p1 = C + (slab + mrow + 8) * 32 + 2 * t;
        } else {
            const size_t r0 = SCATTER ? (size_t)win_src_index(mrow)     : (size_t)mrow;
            const size_t r1 = SCATTER ? (size_t)win_src_index(mrow + 8) : (size_t)(mrow + 8);
            p0 = C + r0 * N_TOTAL + ncolb + 2 * t;
            p1 = C + r1 * N_TOTAL + ncolb + 2 * t;
        }
#pragma unroll
        for (int j = 0; j < 4; j++) {
            float x0 = c[i][j][0] + bj[j].x, y0 = c[i][j][1] + bj[j].y;
            float x1 = c[i][j][2] + bj[j].x, y1 = c[i][j][3] + bj[j].y;
            if (sizeof(CT) == 2) {
                *reinterpret_cast<__half2*>(p0 + j * 8) = __floats2half2_rn(x0, y0);
                *reinterpret_cast<__half2*>(p1 + j * 8) = __floats2half2_rn(x1, y1);
            } else {
                *reinterpret_cast<float2*>(p0 + j * 8) = make_float2(x0, y0);
                *reinterpret_cast<float2*>(p1 + j * 8) = make_float2(x1, y1);
            }
        }
    }
}

// ---------------------------------------------------------------------------
// Preprocessing (natural k order)
__global__ void transpose_half(const float* __restrict__ W, __half* __restrict__ WT,
                               int K, int N)
{
    __shared__ float tbuf[32][33];
    const int n0 = blockIdx.x * 32, k0 = blockIdx.y * 32;
    const int tx = threadIdx.x, ty = threadIdx.y;
#pragma unroll
    for (int i = 0; i < 4; i++)
        tbuf[ty + 8 * i][tx] = W[(size_t)(k0 + ty + 8 * i) * N + n0 + tx];
    __syncthreads();
#pragma unroll
    for (int i = 0; i < 4; i++)
        WT[(size_t)(n0 + ty + 8 * i) * K + k0 + tx] = __float2half_rn(tbuf[tx][ty + 8 * i]);
}

__global__ void x_to_half(const float4* __restrict__ in, uint4* __restrict__ out, int n8)
{
    int i = blockIdx.x * blockDim.x + threadIdx.x;
    if (i < n8) {
        float4 v0 = in[2 * i], v1 = in[2 * i + 1];
        __half2 o[4];
        o[0] = __floats2half2_rn(v0.x, v0.y);
        o[1] = __floats2half2_rn(v0.z, v0.w);
        o[2] = __floats2half2_rn(v1.x, v1.y);
        o[3] = __floats2half2_rn(v1.z, v1.w);
        out[i] = *reinterpret_cast<uint4*>(o);
    }
}

// ---------------------------------------------------------------------------
// fp16 flash-style window attention (R12 verbatim): one warp per (win,head).
__global__ void __launch_bounds__(32)
attn_h_kernel(const float* __restrict__ bias_table)
{
    const int head = blockIdx.x % HEADS;
    const int win  = blockIdx.x / HEADS;
    const int lane = threadIdx.x;
    const int g = lane >> 2, t = lane & 3;

    __shared__ __half SQ[64 * 40];
    __shared__ __half SK[56 * 40];
    __shared__ __half SVr[49 * 40];
    __shared__ __half SVt[32 * 72];
    __shared__ float  Bb[224];

    for (int i = lane; i < 224; i += 32) Bb[i] = 0.f;
    __syncwarp();
    for (int i = lane; i < 169; i += 32) Bb[13 + i] = __ldg(&bias_table[i * HEADS + head]);

    {
        const uint4 z = make_uint4(0, 0, 0, 0);
        uint4* v4 = reinterpret_cast<uint4*>(SVt);
        for (int i = lane; i < 32 * 72 * 2 / 16; i += 32) v4[i] = z;
    }

    const size_t mb = (size_t)win * NTOK;
    const __half* qs = g_qkv + ((size_t)(0 * HEADS + head) * M_TOTAL + mb) * 32;
    const __half* ks = g_qkv + ((size_t)(1 * HEADS + head) * M_TOTAL + mb) * 32;
    const __half* vs = g_qkv + ((size_t)(2 * HEADS + head) * M_TOTAL + mb) * 32;
    const uint32_t sq = smem_u32(SQ), sk = smem_u32(SK), sv = smem_u32(SVr);
    for (int i = lane; i < NTOK * 4; i += 32) {
        int row = i >> 2, seg = i & 3;
        uint32_t so = (uint32_t)row * 80 + seg * 16;
        CP16(sq + so, qs + (size_t)row * 32 + seg * 8);
        CP16(sk + so, ks + (size_t)row * 32 + seg * 8);
        CP16(sv + so, vs + (size_t)row * 32 + seg * 8);
    }
    CP_COMMIT(); CP_WAIT0();
    __syncwarp();

    for (int tok = lane; tok < NTOK; tok += 32) {
#pragma unroll
        for (int d = 0; d < 32; d++)
            SVt[d * 72 + tok] = SVr[tok * 40 + d];
    }
    __syncwarp();

    float c[4][7][4];
#pragma unroll
    for (int it = 0; it < 4; it++)
#pragma unroll
        for (int jt = 0; jt < 7; jt++)
#pragma unroll
            for (int q = 0; q < 4; q++) c[it][jt][q] = 0.f;

#pragma unroll
    for (int kt = 0; kt < 2; kt++) {
        const int ko = kt * 16;
        uint32_t a[4][4];
#pragma unroll
        for (int it = 0; it < 4; it++) {
            a[it][0] = *reinterpret_cast<const uint32_t*>(&SQ[(it * 16 + g)     * 40 + ko + 2 * t]);
            a[it][1] = *reinterpret_cast<const uint32_t*>(&SQ[(it * 16 + g + 8) * 40 + ko + 2 * t]);
            a[it][2] = *reinterpret_cast<const uint32_t*>(&SQ[(it * 16 + g)     * 40 + ko + 8 + 2 * t]);
            a[it][3] = *reinterpret_cast<const uint32_t*>(&SQ[(it * 16 + g + 8) * 40 + ko + 8 + 2 * t]);
        }
#pragma unroll
        for (int jt = 0; jt < 7; jt++) {
            uint32_t b0 = *reinterpret_cast<const uint32_t*>(&SK[(jt * 8 + g) * 40 + ko + 2 * t]);
            uint32_t b1 = *reinterpret_cast<const uint32_t*>(&SK[(jt * 8 + g) * 40 + ko + 8 + 2 * t]);
#pragma unroll
            for (int it = 0; it < 4; it++)
                MMA_F16(c[it][jt], a[it][0], a[it][1], a[it][2], a[it][3], b0, b1);
        }
    }

    const float scale = 0.17677669529663687f;
    int  pi[8];  bool rok[8];
#pragma unroll
    for (int s = 0; s < 8; s++) {
        int tok = (s >> 1) * 16 + g + 8 * (s & 1);
        rok[s] = tok < NTOK;
        int ri = tok / 7, ci = tok - ri * 7;
        pi[s] = ri * 13 + ci + 97;
    }
    int  pj[14]; bool cok[14];
#pragma unroll
    for (int u = 0; u < 14; u++) {
        int jc = (u >> 1) * 8 + 2 * t + (u & 1);
        cok[u] = jc < NTOK;
        int rj = jc / 7, cj = jc - rj * 7;
        pj[u] = rj * 13 + cj;
    }
#pragma unroll
    for (int it = 0; it < 4; it++)
#pragma unroll
        for (int jt = 0; jt < 7; jt++)
#pragma unroll
            for (int q = 0; q < 4; q++) {
                int s = it * 2 + (q >> 1), u = jt * 2 + (q & 1);
                float sc = c[it][jt][q] * scale + Bb[pi[s] - pj[u]];
                c[it][jt][q] = (rok[s] && cok[u]) ? sc : -1e9f;
            }

#pragma unroll
    for (int s = 0; s < 8; s++) {
        const int it = s >> 1, h = s & 1;
        float m = -1e9f;
#pragma unroll
        for (int jt = 0; jt < 7; jt++) {
            m = fmaxf(m, c[it][jt][h * 2]);
            m = fmaxf(m, c[it][jt][h * 2 + 1]);
        }
        m = fmaxf(m, __shfl_xor_sync(0xffffffffu, m, 1));
        m = fmaxf(m, __shfl_xor_sync(0xffffffffu, m, 2));
        float sum = 0.f;
#pragma unroll
        for (int jt = 0; jt < 7; jt++) {
            float p0 = __expf(c[it][jt][h * 2]     - m);
            float p1 = __expf(c[it][jt][h * 2 + 1] - m);
            c[it][jt][h * 2] = p0; c[it][jt][h * 2 + 1] = p1;
            sum += p0 + p1;
        }
        sum += __shfl_xor_sync(0xffffffffu, sum, 1);
        sum += __shfl_xor_sync(0xffffffffu, sum, 2);
        const float inv = 1.0f / sum;
#pragma unroll
        for (int jt = 0; jt < 7; jt++) {
            c[it][jt][h * 2]     *= inv;
            c[it][jt][h * 2 + 1] *= inv;
        }
    }

    uint32_t pa[4][4][4];
#pragma unroll
    for (int it = 0; it < 4; it++)
#pragma unroll
        for (int kt = 0; kt < 4; kt++) {
            const int jt0 = 2 * kt, jt1 = 2 * kt + 1;
            __half2 h0 = __floats2half2_rn(c[it][jt0][0], c[it][jt0][1]);
            __half2 h1 = __floats2half2_rn(c[it][jt0][2], c[it][jt0][3]);
            pa[it][kt][0] = *reinterpret_cast<uint32_t*>(&h0);
            pa[it][kt][1] = *reinterpret_cast<uint32_t*>(&h1);
            if (jt1 < 7) {
                __half2 h2 = __floats2half2_rn(c[it][jt1][0], c[it][jt1][1]);
                __half2 h3 = __floats2half2_rn(c[it][jt1][2], c[it][jt1][3]);
                pa[it][kt][2] = *reinterpret_cast<uint32_t*>(&h2);
                pa[it][kt][3] = *reinterpret_cast<uint32_t*>(&h3);
            } else {
                pa[it][kt][2] = 0u;
                pa[it][kt][3] = 0u;
            }
        }

    float d[4][4][4];
#pragma unroll
    for (int it = 0; it < 4; it++)
#pragma unroll
        for (int nt = 0; nt < 4; nt++)
#pragma unroll
            for (int q = 0; q < 4; q++) d[it][nt][q] = 0.f;

#pragma unroll
    for (int kt = 0; kt < 4; kt++) {
        const int ko = kt * 16;
        uint32_t b[4][2];
#pragma unroll
        for (int nt = 0; nt < 4; nt++) {
            b[nt][0] = *reinterpret_cast<const uint32_t*>(&SVt[(nt * 8 + g) * 72 + ko + 2 * t]);
            b[nt][1] = *reinterpret_cast<const uint32_t*>(&SVt[(nt * 8 + g) * 72 + ko + 8 + 2 * t]);
        }
#pragma unroll
        for (int it = 0; it < 4; it++)
#pragma unroll
            for (int nt = 0; nt < 4; nt++)
                MMA_F16(d[it][nt], pa[it][kt][0], pa[it][kt][1], pa[it][kt][2], pa[it][kt][3],
                        b[nt][0], b[nt][1]);
    }

    __half* obase = g_attn + (size_t)(win * NTOK) * N_PROJ + head * 32;
#pragma unroll
    for (int it = 0; it < 4; it++)
#pragma unroll
        for (int qq = 0; qq < 2; qq++) {
            int tok = it * 16 + g + 8 * qq;
            if (tok < NTOK) {
                __half* orow = obase + (size_t)tok * N_PROJ;
#pragma unroll
                for (int nt = 0; nt < 4; nt++) {
                    __half2 hv = __floats2half2_rn(d[it][nt][2 * qq], d[it][nt][2 * qq + 1]);
                    *reinterpret_cast<__half2*>(&orow[nt * 8 + 2 * t]) = hv;
                }
            }
        }
}

// ---------------------------------------------------------------------------
extern "C" void kernel_launch(void* const* d_in, const int* in_sizes, int n_in,
                              void* d_out, int out_size)
{
    const float* x          = (const float*)d_in[0];
    const float* qkv_w      = (const float*)d_in[1];
    const float* qkv_b      = (const float*)d_in[2];
    const float* proj_w     = (const float*)d_in[3];
    const float* proj_b     = (const float*)d_in[4];
    const float* bias_table = (const float*)d_in[5];
    float* out = (float*)d_out;

    __half *qkv_p, *attn_p, *xh_p, *wtq_p, *wtp_p;
    cudaGetSymbolAddress((void**)&qkv_p,  g_qkv);
    cudaGetSymbolAddress((void**)&attn_p, g_attn);
    cudaGetSymbolAddress((void**)&xh_p,   g_xh);
    cudaGetSymbolAddress((void**)&wtq_p,  g_wtq);
    cudaGetSymbolAddress((void**)&wtp_p,  g_wtp);

    cudaFuncSetAttribute((const void*)gemm_h<N_QKV, true, false, true, __half>,
                         cudaFuncAttributeMaxDynamicSharedMemorySize, SMEM_BYTES);
    cudaFuncSetAttribute((const void*)gemm_h<N_PROJ, false, true, false, float>,
                         cudaFuncAttributeMaxDynamicSharedMemorySize, SMEM_BYTES);

    // 0) preprocessing
    {
        int n8 = M_TOTAL * KDIM / 8;
        x_to_half<<<(n8 + 255) / 256, 256>>>((const float4*)x, (uint4*)xh_p, n8);
        transpose_half<<<dim3(N_QKV / 32, KDIM / 32), dim3(32, 8)>>>(qkv_w, wtq_p, KDIM, N_QKV);
        transpose_half<<<dim3(N_PROJ / 32, KDIM / 32), dim3(32, 8)>>>(proj_w, wtp_p, KDIM, N_PROJ);
    }
    // 1) QKV GEMM (fp16 mma + ldmatrix, fused gather, head-major slab output)
    gemm_h<N_QKV, true, false, true, __half><<<dim3(N_QKV / BN, M_TOTAL / BM), 256, SMEM_BYTES>>>(
        xh_p, wtq_p, qkv_b, qkv_p);
    // 2) fp16 flash-style window attention
    attn_h_kernel<<<NWIN * HEADS, 32>>>(bias_table);
    // 3) proj GEMM (fp16 mma + ldmatrix, fused inverse roll/window scatter)
    gemm_h<N_PROJ, false, true, false, float><<<dim3(N_PROJ / BN, M_TOTAL / BM), 256, SMEM_BYTES>>>(
        attn_p, wtp_p, proj_b, out);
}

// round 14
// speedup vs baseline: 1.1583x; 1.1583x over previous
#include <cuda_runtime.h>
#include <cuda_fp16.h>
#include <cstdint>

// Problem constants (B=32, H=W=56, C=384, heads=12, ws=7, shift=3)
#define HEADS   12
#define WS      7
#define NTOK    49
#define NWIN    2048
#define M_TOTAL (NWIN * NTOK)   // 100352
#define N_QKV   1152
#define N_PROJ  384
#define KDIM    384

// fp16 GEMM tiling (R12 shape): CTA 128x128, 256 threads (8 warps, 64x32 warp
// tile), BK=32 halfs (12 K-steps), FIVE-stage cp.async ring, ldmatrix frags.
#define BM 128
#define BN 128
#define BK 32
#define KSTEPS (KDIM / BK)        // 12
#define ROW_HALF 40               // halfs per smem row (32 used + 8 pad) = 80B
#define OP_BYTES (BM * ROW_HALF * 2)      // 10240 B per operand per stage
#define STAGE_BYTES (2 * OP_BYTES)        // 20480
#define NSTG 5
#define SMEM_BYTES (NSTG * STAGE_BYTES)   // 102400 (2 CTAs = 204.8KB <= 228KB)

// Scratch. g_qkv holds qkv output in HEAD-MAJOR slabs [tensor*12+head][m][32].
__device__ __half g_qkv[(size_t)M_TOTAL * N_QKV];
__device__ __half g_attn[(size_t)M_TOTAL * N_PROJ];
__device__ __half g_xh [(size_t)M_TOTAL * KDIM];
__device__ __half g_wtq[(size_t)N_QKV * KDIM];
__device__ __half g_wtp[(size_t)N_PROJ * KDIM];

// ---------------------------------------------------------------------------
__device__ __forceinline__ int win_src_index(int m) {
    int win = m / NTOK, t = m - win * NTOK;
    int b  = win >> 6, wi = win & 63;
    int wh = wi >> 3,  ww = wi & 7;
    int r  = t / WS,   c  = t - r * WS;
    int row = wh * WS + r + 3; if (row >= 56) row -= 56;
    int col = ww * WS + c + 3; if (col >= 56) col -= 56;
    return b * 3136 + row * 56 + col;
}

__device__ __forceinline__ uint32_t smem_u32(const void* p) {
    uint32_t a;
    asm("{ .reg .u64 t; cvta.to.shared.u64 t, %1; cvt.u32.u64 %0, t; }" : "=r"(a) : "l"(p));
    return a;
}

#define CP16(dst, src) \
    asm volatile("cp.async.cg.shared.global [%0], [%1], 16;" :: "r"(dst), "l"(src) : "memory")
#define CP_COMMIT() asm volatile("cp.async.commit_group;" ::: "memory")
#define CP_WAIT3()  asm volatile("cp.async.wait_group 3;" ::: "memory")
#define CP_WAIT2()  asm volatile("cp.async.wait_group 2;" ::: "memory")
#define CP_WAIT1()  asm volatile("cp.async.wait_group 1;" ::: "memory")
#define CP_WAIT0()  asm volatile("cp.async.wait_group 0;" ::: "memory")

#define MMA_F16(c, a0, a1, a2, a3, b0, b1) \
    asm volatile("mma.sync.aligned.m16n8k16.row.col.f32.f16.f16.f32 " \
        "{%0,%1,%2,%3}, {%4,%5,%6,%7}, {%8,%9}, {%0,%1,%2,%3};" \
        : "+f"((c)[0]), "+f"((c)[1]), "+f"((c)[2]), "+f"((c)[3]) \
        : "r"(a0), "r"(a1), "r"(a2), "r"(a3), "r"(b0), "r"(b1))

#define LDSM_X4(r0, r1, r2, r3, addr) \
    asm volatile("ldmatrix.sync.aligned.m8n8.x4.shared.b16 {%0,%1,%2,%3}, [%4];" \
        : "=r"(r0), "=r"(r1), "=r"(r2), "=r"(r3) : "r"(addr))

// ---------------------------------------------------------------------------
// fp16 mma.sync GEMM (fp32 accum), ldmatrix fragment loads, 5-stage ring.
// GATHER: fuse roll/window map into A rows. HEADOUT: [ncol/32][m][32] slab
// output (qkv). SCATTER: fuse inverse roll/window into output rows (proj).
template <int N_TOTAL, bool GATHER, bool SCATTER, bool HEADOUT, typename CT>
__global__ void __launch_bounds__(256, 2)
gemm_h(const __half* __restrict__ A, const __half* __restrict__ WT,
       const float* __restrict__ bias, CT* __restrict__ C)
{
    extern __shared__ __half smh[];
    const uint32_t smb = smem_u32(smh);

    const int tid  = threadIdx.x;
    const int wid  = tid >> 5, lane = tid & 31;
    const int t    = lane & 3;
    const int wm   = wid & 1, wn = wid >> 1;     // warp grid 2(M) x 4(N)
    const int m0   = blockIdx.y * BM, n0 = blockIdx.x * BN;

    // gmem->smem: 2 threads per row, 16 halfs (32B = 2x CP16) each
    const int lrow = tid >> 1, lseg = (tid & 1) * 16;
    const __half* arow = A + (size_t)(GATHER ? win_src_index(m0 + lrow) : (m0 + lrow)) * KDIM + lseg;
    const __half* brow = WT + (size_t)(n0 + lrow) * KDIM + lseg;
    const uint32_t a_dst = smb + (uint32_t)lrow * (ROW_HALF * 2) + lseg * 2;
    const uint32_t b_dst = a_dst + OP_BYTES;

    auto load_stage = [&](int s, int kt) {
        const uint32_t so = (uint32_t)s * STAGE_BYTES;
        const __half* ap = arow + kt * BK;
        const __half* bp = brow + kt * BK;
        CP16(a_dst + so,      ap);
        CP16(a_dst + so + 16, ap + 8);
        CP16(b_dst + so,      bp);
        CP16(b_dst + so + 16, bp + 8);
    };

    // ldmatrix lane addressing (x4 = four 8x8 b16 tiles)
    const int l7  = lane & 7;
    const int l8  = (lane >> 3) & 1;
    const int l16 = (lane >> 4) & 1;
    uint32_t a_addr[4];
#pragma unroll
    for (int it = 0; it < 4; it++)
        a_addr[it] = smb + (uint32_t)(((wm * 64 + it * 16 + l7 + l8 * 8) * ROW_HALF + l16 * 8) * 2);
    uint32_t b_addr[2];
#pragma unroll
    for (int jp = 0; jp < 2; jp++)
        b_addr[jp] = smb + OP_BYTES
                   + (uint32_t)(((wn * 32 + jp * 16 + l16 * 8 + l7) * ROW_HALF + l8 * 8) * 2);

    float c[4][4][4];
#pragma unroll
    for (int i = 0; i < 4; i++)
#pragma unroll
        for (int j = 0; j < 4; j++)
#pragma unroll
            for (int q = 0; q < 4; q++) c[i][j][q] = 0.f;

#pragma unroll
    for (int s = 0; s < NSTG - 1; s++) { load_stage(s, s); CP_COMMIT(); }

    int sidx = 0;   // kt % 5
    for (int kt = 0; kt < KSTEPS; kt++) {
        const int rem = KSTEPS - 1 - kt;
        if (rem >= 3)      CP_WAIT3();
        else if (rem == 2) CP_WAIT2();
        else if (rem == 1) CP_WAIT1();
        else               CP_WAIT0();
        __syncthreads();

        if (kt + NSTG - 1 < KSTEPS) {
            int ps = sidx - 1; if (ps < 0) ps += NSTG;   // (kt+4)%5 == (kt-1)%5
            load_stage(ps, kt + NSTG - 1); CP_COMMIT();
        }

        const uint32_t soff = (uint32_t)sidx * STAGE_BYTES;
        if (++sidx == NSTG) sidx = 0;

#pragma unroll
        for (int ks = 0; ks < 2; ks++) {          // two k16 sub-steps per BK=32
            const uint32_t ko = soff + ks * 32;   // 16 halfs = 32 bytes
            uint32_t b[2][4];
#pragma unroll
            for (int jp = 0; jp < 2; jp++)
                LDSM_X4(b[jp][0], b[jp][1], b[jp][2], b[jp][3], b_addr[jp] + ko);
            uint32_t a[4][4];
#pragma unroll
            for (int it = 0; it < 4; it++)
                LDSM_X4(a[it][0], a[it][1], a[it][2], a[it][3], a_addr[it] + ko);
#pragma unroll
            for (int it = 0; it < 4; it++)
#pragma unroll
                for (int jt = 0; jt < 4; jt++)
                    MMA_F16(c[it][jt], a[it][0], a[it][1], a[it][2], a[it][3],
                            b[jt >> 1][2 * (jt & 1)], b[jt >> 1][2 * (jt & 1) + 1]);
        }
    }

    // epilogue: fp32 bias add; each 4-lane group stores 32B contiguous
    const int g = lane >> 2;
    const int ncolb = n0 + wn * 32;
    float2 bj[4];
#pragma unroll
    for (int j = 0; j < 4; j++)
        bj[j] = *reinterpret_cast<const float2*>(&bias[ncolb + j * 8 + 2 * t]);

#pragma unroll
    for (int i = 0; i < 4; i++) {
        const int mrow = m0 + wm * 64 + i * 16 + g;
        CT *p0, *p1;
        if (HEADOUT) {
            const size_t slab = (size_t)(ncolb >> 5) * M_TOTAL;
            p0 = C + (slab + mrow)     * 32 + 2 * t;
            p1 = C + (slab + mrow + 8) * 32 + 2 * t;
        } else {
            const size_t r0 = SCATTER ? (size_t)win_src_index(mrow)     : (size_t)mrow;
            const size_t r1 = SCATTER ? (size_t)win_src_index(mrow + 8) : (size_t)(mrow + 8);
            p0 = C + r0 * N_TOTAL + ncolb + 2 * t;
            p1 = C + r1 * N_TOTAL + ncolb + 2 * t;
        }
#pragma unroll
        for (int j = 0; j < 4; j++) {
            float x0 = c[i][j][0] + bj[j].x, y0 = c[i][j][1] + bj[j].y;
            float x1 = c[i][j][2] + bj[j].x, y1 = c[i][j][3] + bj[j].y;
            if (sizeof(CT) == 2) {
                *reinterpret_cast<__half2*>(p0 + j * 8) = __floats2half2_rn(x0, y0);
                *reinterpret_cast<__half2*>(p1 + j * 8) = __floats2half2_rn(x1, y1);
            } else {
                *reinterpret_cast<float2*>(p0 + j * 8) = make_float2(x0, y0);
                *reinterpret_cast<float2*>(p1 + j * 8) = make_float2(x1, y1);
            }
        }
    }
}

// ---------------------------------------------------------------------------
// Preprocessing (natural k order)
__global__ void transpose_half(const float* __restrict__ W, __half* __restrict__ WT,
                               int K, int N)
{
    __shared__ float tbuf[32][33];
    const int n0 = blockIdx.x * 32, k0 = blockIdx.y * 32;
    const int tx = threadIdx.x, ty = threadIdx.y;
#pragma unroll
    for (int i = 0; i < 4; i++)
        tbuf[ty + 8 * i][tx] = W[(size_t)(k0 + ty + 8 * i) * N + n0 + tx];
    __syncthreads();
#pragma unroll
    for (int i = 0; i < 4; i++)
        WT[(size_t)(n0 + ty + 8 * i) * K + k0 + tx] = __float2half_rn(tbuf[tx][ty + 8 * i]);
}

__global__ void x_to_half(const float4* __restrict__ in, uint4* __restrict__ out, int n8)
{
    int i = blockIdx.x * blockDim.x + threadIdx.x;
    if (i < n8) {
        float4 v0 = in[2 * i], v1 = in[2 * i + 1];
        __half2 o[4];
        o[0] = __floats2half2_rn(v0.x, v0.y);
        o[1] = __floats2half2_rn(v0.z, v0.w);
        o[2] = __floats2half2_rn(v1.x, v1.y);
        o[3] = __floats2half2_rn(v1.z, v1.w);
        out[i] = *reinterpret_cast<uint4*>(o);
    }
}

// ---------------------------------------------------------------------------
// fp16 flash-style window attention (R12 verbatim): one warp per (win,head).
__global__ void __launch_bounds__(32)
attn_h_kernel(const float* __restrict__ bias_table)
{
    const int head = blockIdx.x % HEADS;
    const int win  = blockIdx.x / HEADS;
    const int lane = threadIdx.x;
    const int g = lane >> 2, t = lane & 3;

    __shared__ __half SQ[64 * 40];
    __shared__ __half SK[56 * 40];
    __shared__ __half SVr[49 * 40];
    __shared__ __half SVt[32 * 72];
    __shared__ float  Bb[224];

    for (int i = lane; i < 224; i += 32) Bb[i] = 0.f;
    __syncwarp();
    for (int i = lane; i < 169; i += 32) Bb[13 + i] = __ldg(&bias_table[i * HEADS + head]);

    {
        const uint4 z = make_uint4(0, 0, 0, 0);
        uint4* v4 = reinterpret_cast<uint4*>(SVt);
        for (int i = lane; i < 32 * 72 * 2 / 16; i += 32) v4[i] = z;
    }

    const size_t mb = (size_t)win * NTOK;
    const __half* qs = g_qkv + ((size_t)(0 * HEADS + head) * M_TOTAL + mb) * 32;
    const __half* ks = g_qkv + ((size_t)(1 * HEADS + head) * M_TOTAL + mb) * 32;
    const __half* vs = g_qkv + ((size_t)(2 * HEADS + head) * M_TOTAL + mb) * 32;
    const uint32_t sq = smem_u32(SQ), sk = smem_u32(SK), sv = smem_u32(SVr);
    for (int i = lane; i < NTOK * 4; i += 32) {
        int row = i >> 2, seg = i & 3;
        uint32_t so = (uint32_t)row * 80 + seg * 16;
        CP16(sq + so, qs + (size_t)row * 32 + seg * 8);
        CP16(sk + so, ks + (size_t)row * 32 + seg * 8);
        CP16(sv + so, vs + (size_t)row * 32 + seg * 8);
    }
    CP_COMMIT(); CP_WAIT0();
    __syncwarp();

    for (int tok = lane; tok < NTOK; tok += 32) {
#pragma unroll
        for (int d = 0; d < 32; d++)
            SVt[d * 72 + tok] = SVr[tok * 40 + d];
    }
    __syncwarp();

    float c[4][7][4];
#pragma unroll
    for (int it = 0; it < 4; it++)
#pragma unroll
        for (int jt = 0; jt < 7; jt++)
#pragma unroll
            for (int q = 0; q < 4; q++) c[it][jt][q] = 0.f;

#pragma unroll
    for (int kt = 0; kt < 2; kt++) {
        const int ko = kt * 16;
        uint32_t a[4][4];
#pragma unroll
        for (int it = 0; it < 4; it++) {
            a[it][0] = *reinterpret_cast<const uint32_t*>(&SQ[(it * 16 + g)     * 40 + ko + 2 * t]);
            a[it][1] = *reinterpret_cast<const uint32_t*>(&SQ[(it * 16 + g + 8) * 40 + ko + 2 * t]);
            a[it][2] = *reinterpret_cast<const uint32_t*>(&SQ[(it * 16 + g)     * 40 + ko + 8 + 2 * t]);
            a[it][3] = *reinterpret_cast<const uint32_t*>(&SQ[(it * 16 + g + 8) * 40 + ko + 8 + 2 * t]);
        }
#pragma unroll
        for (int jt = 0; jt < 7; jt++) {
            uint32_t b0 = *reinterpret_cast<const uint32_t*>(&SK[(jt * 8 + g) * 40 + ko + 2 * t]);
            uint32_t b1 = *reinterpret_cast<const uint32_t*>(&SK[(jt * 8 + g) * 40 + ko + 8 + 2 * t]);
#pragma unroll
            for (int it = 0; it < 4; it++)
                MMA_F16(c[it][jt], a[it][0], a[it][1], a[it][2], a[it][3], b0, b1);
        }
    }

    const float scale = 0.17677669529663687f;
    int  pi[8];  bool rok[8];
#pragma unroll
    for (int s = 0; s < 8; s++) {
        int tok = (s >> 1) * 16 + g + 8 * (s & 1);
        rok[s] = tok < NTOK;
        int ri = tok / 7, ci = tok - ri * 7;
        pi[s] = ri * 13 + ci + 97;
    }
    int  pj[14]; bool cok[14];
#pragma unroll
    for (int u = 0; u < 14; u++) {
        int jc = (u >> 1) * 8 + 2 * t + (u & 1);
        cok[u] = jc < NTOK;
        int rj = jc / 7, cj = jc - rj * 7;
        pj[u] = rj * 13 + cj;
    }
#pragma unroll
    for (int it = 0; it < 4; it++)
#pragma unroll
        for (int jt = 0; jt < 7; jt++)
#pragma unroll
            for (int q = 0; q < 4; q++) {
                int s = it * 2 + (q >> 1), u = jt * 2 + (q & 1);
                float sc = c[it][jt][q] * scale + Bb[pi[s] - pj[u]];
                c[it][jt][q] = (rok[s] && cok[u]) ? sc : -1e9f;
            }

#pragma unroll
    for (int s = 0; s < 8; s++) {
        const int it = s >> 1, h = s & 1;
        float m = -1e9f;
#pragma unroll
        for (int jt = 0; jt < 7; jt++) {
            m = fmaxf(m, c[it][jt][h * 2]);
            m = fmaxf(m, c[it][jt][h * 2 + 1]);
        }
        m = fmaxf(m, __shfl_xor_sync(0xffffffffu, m, 1));
        m = fmaxf(m, __shfl_xor_sync(0xffffffffu, m, 2));
        float sum = 0.f;
#pragma unroll
        for (int jt = 0; jt < 7; jt++) {
            float p0 = __expf(c[it][jt][h * 2]     - m);
            float p1 = __expf(c[it][jt][h * 2 + 1] - m);
            c[it][jt][h * 2] = p0; c[it][jt][h * 2 + 1] = p1;
            sum += p0 + p1;
        }
        sum += __shfl_xor_sync(0xffffffffu, sum, 1);
        sum += __shfl_xor_sync(0xffffffffu, sum, 2);
        const float inv = 1.0f / sum;
#pragma unroll
        for (int jt = 0; jt < 7; jt++) {
            c[it][jt][h * 2]     *= inv;
            c[it][jt][h * 2 + 1] *= inv;
        }
    }

    uint32_t pa[4][4][4];
#pragma unroll
    for (int it = 0; it < 4; it++)
#pragma unroll
        for (int kt = 0; kt < 4; kt++) {
            const int jt0 = 2 * kt, jt1 = 2 * kt + 1;
            __half2 h0 = __floats2half2_rn(c[it][jt0][0], c[it][jt0][1]);
            __half2 h1 = __floats2half2_rn(c[it][jt0][2], c[it][jt0][3]);
            pa[it][kt][0] = *reinterpret_cast<uint32_t*>(&h0);
            pa[it][kt][1] = *reinterpret_cast<uint32_t*>(&h1);
            if (jt1 < 7) {
                __half2 h2 = __floats2half2_rn(c[it][jt1][0], c[it][jt1][1]);
                __half2 h3 = __floats2half2_rn(c[it][jt1][2], c[it][jt1][3]);
                pa[it][kt][2] = *reinterpret_cast<uint32_t*>(&h2);
                pa[it][kt][3] = *reinterpret_cast<uint32_t*>(&h3);
            } else {
                pa[it][kt][2] = 0u;
                pa[it][kt][3] = 0u;
            }
        }

    float d[4][4][4];
#pragma unroll
    for (int it = 0; it < 4; it++)
#pragma unroll
        for (int nt = 0; nt < 4; nt++)
#pragma unroll
            for (int q = 0; q < 4; q++) d[it][nt][q] = 0.f;

#pragma unroll
    for (int kt = 0; kt < 4; kt++) {
        const int ko = kt * 16;
        uint32_t b[4][2];
#pragma unroll
        for (int nt = 0; nt < 4; nt++) {
            b[nt][0] = *reinterpret_cast<const uint32_t*>(&SVt[(nt * 8 + g) * 72 + ko + 2 * t]);
            b[nt][1] = *reinterpret_cast<const uint32_t*>(&SVt[(nt * 8 + g) * 72 + ko + 8 + 2 * t]);
        }
#pragma unroll
        for (int it = 0; it < 4; it++)
#pragma unroll
            for (int nt = 0; nt < 4; nt++)
                MMA_F16(d[it][nt], pa[it][kt][0], pa[it][kt][1], pa[it][kt][2], pa[it][kt][3],
                        b[nt][0], b[nt][1]);
    }

    __half* obase = g_attn + (size_t)(win * NTOK) * N_PROJ + head * 32;
#pragma unroll
    for (int it = 0; it < 4; it++)
#pragma unroll
        for (int qq = 0; qq < 2; qq++) {
            int tok = it * 16 + g + 8 * qq;
            if (tok < NTOK) {
                __half* orow = obase + (size_t)tok * N_PROJ;
#pragma unroll
                for (int nt = 0; nt < 4; nt++) {
                    __half2 hv = __floats2half2_rn(d[it][nt][2 * qq], d[it][nt][2 * qq + 1]);
                    *reinterpret_cast<__half2*>(&orow[nt * 8 + 2 * t]) = hv;
                }
            }
        }
}

// ---------------------------------------------------------------------------
extern "C" void kernel_launch(void* const* d_in, const int* in_sizes, int n_in,
                              void* d_out, int out_size)
{
    const float* x          = (const float*)d_in[0];
    const float* qkv_w      = (const float*)d_in[1];
    const float* qkv_b      = (const float*)d_in[2];
    const float* proj_w     = (const float*)d_in[3];
    const float* proj_b     = (const float*)d_in[4];
    const float* bias_table = (const float*)d_in[5];
    float* out = (float*)d_out;

    __half *qkv_p, *attn_p, *xh_p, *wtq_p, *wtp_p;
    cudaGetSymbolAddress((void**)&qkv_p,  g_qkv);
    cudaGetSymbolAddress((void**)&attn_p, g_attn);
    cudaGetSymbolAddress((void**)&xh_p,   g_xh);
    cudaGetSymbolAddress((void**)&wtq_p,  g_wtq);
    cudaGetSymbolAddress((void**)&wtp_p,  g_wtp);

    cudaFuncSetAttribute((const void*)gemm_h<N_QKV, true, false, true, __half>,
                         cudaFuncAttributeMaxDynamicSharedMemorySize, SMEM_BYTES);
    cudaFuncSetAttribute((const void*)gemm_h<N_PROJ, false, true, false, float>,
                         cudaFuncAttributeMaxDynamicSharedMemorySize, SMEM_BYTES);

    // 0) preprocessing
    {
        int n8 = M_TOTAL * KDIM / 8;
        x_to_half<<<(n8 + 255) / 256, 256>>>((const float4*)x, (uint4*)xh_p, n8);
        transpose_half<<<dim3(N_QKV / 32, KDIM / 32), dim3(32, 8)>>>(qkv_w, wtq_p, KDIM, N_QKV);
        transpose_half<<<dim3(N_PROJ / 32, KDIM / 32), dim3(32, 8)>>>(proj_w, wtp_p, KDIM, N_PROJ);
    }
    // 1) QKV GEMM (fp16 mma + ldmatrix, fused gather, head-major slab output)
    gemm_h<N_QKV, true, false, true, __half><<<dim3(N_QKV / BN, M_TOTAL / BM), 256, SMEM_BYTES>>>(
        xh_p, wtq_p, qkv_b, qkv_p);
    // 2) fp16 flash-style window attention
    attn_h_kernel<<<NWIN * HEADS, 32>>>(bias_table);
    // 3) proj GEMM (fp16 mma + ldmatrix, fused inverse roll/window scatter)
    gemm_h<N_PROJ, false, true, false, float><<<dim3(N_PROJ / BN, M_TOTAL / BM), 256, SMEM_BYTES>>>(
        attn_p, wtp_p, proj_b, out);
}

// round 15
// speedup vs baseline: 1.1760x; 1.0153x over previous
#include <cuda_runtime.h>
#include <cuda_fp16.h>
#include <cstdint>

// Problem constants (B=32, H=W=56, C=384, heads=12, ws=7, shift=3)
#define HEADS   12
#define WS      7
#define NTOK    49
#define NWIN    2048
#define M_TOTAL (NWIN * NTOK)   // 100352
#define N_QKV   1152
#define N_PROJ  384
#define KDIM    384

// fp16 GEMM tiling (R14 known-good): CTA 128x128, 256 threads, BK=32 halfs,
// FIVE-stage cp.async ring, ldmatrix fragment loads.
#define BM 128
#define BN 128
#define BK 32
#define KSTEPS (KDIM / BK)        // 12
#define ROW_HALF 40               // halfs per smem row (32 used + 8 pad) = 80B
#define OP_BYTES (BM * ROW_HALF * 2)      // 10240 B per operand per stage
#define STAGE_BYTES (2 * OP_BYTES)        // 20480
#define NSTG 5
#define SMEM_BYTES (NSTG * STAGE_BYTES)   // 102400 (2 CTAs = 204.8KB <= 228KB)

// Scratch. g_qkv holds qkv output in HEAD-MAJOR slabs [tensor*12+head][m][32].
__device__ __half g_qkv[(size_t)M_TOTAL * N_QKV];
__device__ __half g_attn[(size_t)M_TOTAL * N_PROJ];
__device__ __half g_xh [(size_t)M_TOTAL * KDIM];
__device__ __half g_wtq[(size_t)N_QKV * KDIM];
__device__ __half g_wtp[(size_t)N_PROJ * KDIM];

// ---------------------------------------------------------------------------
__device__ __forceinline__ int win_src_index(int m) {
    int win = m / NTOK, t = m - win * NTOK;
    int b  = win >> 6, wi = win & 63;
    int wh = wi >> 3,  ww = wi & 7;
    int r  = t / WS,   c  = t - r * WS;
    int row = wh * WS + r + 3; if (row >= 56) row -= 56;
    int col = ww * WS + c + 3; if (col >= 56) col -= 56;
    return b * 3136 + row * 56 + col;
}

__device__ __forceinline__ uint32_t smem_u32(const void* p) {
    uint32_t a;
    asm("{ .reg .u64 t; cvta.to.shared.u64 t, %1; cvt.u32.u64 %0, t; }" : "=r"(a) : "l"(p));
    return a;
}

#define CP16(dst, src) \
    asm volatile("cp.async.cg.shared.global [%0], [%1], 16;" :: "r"(dst), "l"(src) : "memory")
#define CP_COMMIT() asm volatile("cp.async.commit_group;" ::: "memory")
#define CP_WAIT3()  asm volatile("cp.async.wait_group 3;" ::: "memory")
#define CP_WAIT2()  asm volatile("cp.async.wait_group 2;" ::: "memory")
#define CP_WAIT1()  asm volatile("cp.async.wait_group 1;" ::: "memory")
#define CP_WAIT0()  asm volatile("cp.async.wait_group 0;" ::: "memory")

#define MMA_F16(c, a0, a1, a2, a3, b0, b1) \
    asm volatile("mma.sync.aligned.m16n8k16.row.col.f32.f16.f16.f32 " \
        "{%0,%1,%2,%3}, {%4,%5,%6,%7}, {%8,%9}, {%0,%1,%2,%3};" \
        : "+f"((c)[0]), "+f"((c)[1]), "+f"((c)[2]), "+f"((c)[3]) \
        : "r"(a0), "r"(a1), "r"(a2), "r"(a3), "r"(b0), "r"(b1))

#define LDSM_X4(r0, r1, r2, r3, addr) \
    asm volatile("ldmatrix.sync.aligned.m8n8.x4.shared.b16 {%0,%1,%2,%3}, [%4];" \
        : "=r"(r0), "=r"(r1), "=r"(r2), "=r"(r3) : "r"(addr))

// ---------------------------------------------------------------------------
// fp16 mma.sync GEMM (fp32 accum), ldmatrix fragment loads, 5-stage ring.
// (R14 verbatim — near the HMMA-path roofline.)
template <int N_TOTAL, bool GATHER, bool SCATTER, bool HEADOUT, typename CT>
__global__ void __launch_bounds__(256, 2)
gemm_h(const __half* __restrict__ A, const __half* __restrict__ WT,
       const float* __restrict__ bias, CT* __restrict__ C)
{
    extern __shared__ __half smh[];
    const uint32_t smb = smem_u32(smh);

    const int tid  = threadIdx.x;
    const int wid  = tid >> 5, lane = tid & 31;
    const int t    = lane & 3;
    const int wm   = wid & 1, wn = wid >> 1;
    const int m0   = blockIdx.y * BM, n0 = blockIdx.x * BN;

    const int lrow = tid >> 1, lseg = (tid & 1) * 16;
    const __half* arow = A + (size_t)(GATHER ? win_src_index(m0 + lrow) : (m0 + lrow)) * KDIM + lseg;
    const __half* brow = WT + (size_t)(n0 + lrow) * KDIM + lseg;
    const uint32_t a_dst = smb + (uint32_t)lrow * (ROW_HALF * 2) + lseg * 2;
    const uint32_t b_dst = a_dst + OP_BYTES;

    auto load_stage = [&](int s, int kt) {
        const uint32_t so = (uint32_t)s * STAGE_BYTES;
        const __half* ap = arow + kt * BK;
        const __half* bp = brow + kt * BK;
        CP16(a_dst + so,      ap);
        CP16(a_dst + so + 16, ap + 8);
        CP16(b_dst + so,      bp);
        CP16(b_dst + so + 16, bp + 8);
    };

    const int l7  = lane & 7;
    const int l8  = (lane >> 3) & 1;
    const int l16 = (lane >> 4) & 1;
    uint32_t a_addr[4];
#pragma unroll
    for (int it = 0; it < 4; it++)
        a_addr[it] = smb + (uint32_t)(((wm * 64 + it * 16 + l7 + l8 * 8) * ROW_HALF + l16 * 8) * 2);
    uint32_t b_addr[2];
#pragma unroll
    for (int jp = 0; jp < 2; jp++)
        b_addr[jp] = smb + OP_BYTES
                   + (uint32_t)(((wn * 32 + jp * 16 + l16 * 8 + l7) * ROW_HALF + l8 * 8) * 2);

    float c[4][4][4];
#pragma unroll
    for (int i = 0; i < 4; i++)
#pragma unroll
        for (int j = 0; j < 4; j++)
#pragma unroll
            for (int q = 0; q < 4; q++) c[i][j][q] = 0.f;

#pragma unroll
    for (int s = 0; s < NSTG - 1; s++) { load_stage(s, s); CP_COMMIT(); }

    int sidx = 0;
    for (int kt = 0; kt < KSTEPS; kt++) {
        const int rem = KSTEPS - 1 - kt;
        if (rem >= 3)      CP_WAIT3();
        else if (rem == 2) CP_WAIT2();
        else if (rem == 1) CP_WAIT1();
        else               CP_WAIT0();
        __syncthreads();

        if (kt + NSTG - 1 < KSTEPS) {
            int ps = sidx - 1; if (ps < 0) ps += NSTG;
            load_stage(ps, kt + NSTG - 1); CP_COMMIT();
        }

        const uint32_t soff = (uint32_t)sidx * STAGE_BYTES;
        if (++sidx == NSTG) sidx = 0;

#pragma unroll
        for (int ks = 0; ks < 2; ks++) {
            const uint32_t ko = soff + ks * 32;
            uint32_t b[2][4];
#pragma unroll
            for (int jp = 0; jp < 2; jp++)
                LDSM_X4(b[jp][0], b[jp][1], b[jp][2], b[jp][3], b_addr[jp] + ko);
            uint32_t a[4][4];
#pragma unroll
            for (int it = 0; it < 4; it++)
                LDSM_X4(a[it][0], a[it][1], a[it][2], a[it][3], a_addr[it] + ko);
#pragma unroll
            for (int it = 0; it < 4; it++)
#pragma unroll
                for (int jt = 0; jt < 4; jt++)
                    MMA_F16(c[it][jt], a[it][0], a[it][1], a[it][2], a[it][3],
                            b[jt >> 1][2 * (jt & 1)], b[jt >> 1][2 * (jt & 1) + 1]);
        }
    }

    const int g = lane >> 2;
    const int ncolb = n0 + wn * 32;
    float2 bj[4];
#pragma unroll
    for (int j = 0; j < 4; j++)
        bj[j] = *reinterpret_cast<const float2*>(&bias[ncolb + j * 8 + 2 * t]);

#pragma unroll
    for (int i = 0; i < 4; i++) {
        const int mrow = m0 + wm * 64 + i * 16 + g;
        CT *p0, *p1;
        if (HEADOUT) {
            const size_t slab = (size_t)(ncolb >> 5) * M_TOTAL;
            p0 = C + (slab + mrow)     * 32 + 2 * t;
            p1 = C + (slab + mrow + 8) * 32 + 2 * t;
        } else {
            const size_t r0 = SCATTER ? (size_t)win_src_index(mrow)     : (size_t)mrow;
            const size_t r1 = SCATTER ? (size_t)win_src_index(mrow + 8) : (size_t)(mrow + 8);
            p0 = C + r0 * N_TOTAL + ncolb + 2 * t;
            p1 = C + r1 * N_TOTAL + ncolb + 2 * t;
        }
#pragma unroll
        for (int j = 0; j < 4; j++) {
            float x0 = c[i][j][0] + bj[j].x, y0 = c[i][j][1] + bj[j].y;
            float x1 = c[i][j][2] + bj[j].x, y1 = c[i][j][3] + bj[j].y;
            if (sizeof(CT) == 2) {
                *reinterpret_cast<__half2*>(p0 + j * 8) = __floats2half2_rn(x0, y0);
                *reinterpret_cast<__half2*>(p1 + j * 8) = __floats2half2_rn(x1, y1);
            } else {
                *reinterpret_cast<float2*>(p0 + j * 8) = make_float2(x0, y0);
                *reinterpret_cast<float2*>(p1 + j * 8) = make_float2(x1, y1);
            }
        }
    }
}

// ---------------------------------------------------------------------------
// Preprocessing (natural k order)
__global__ void transpose_half(const float* __restrict__ W, __half* __restrict__ WT,
                               int K, int N)
{
    __shared__ float tbuf[32][33];
    const int n0 = blockIdx.x * 32, k0 = blockIdx.y * 32;
    const int tx = threadIdx.x, ty = threadIdx.y;
#pragma unroll
    for (int i = 0; i < 4; i++)
        tbuf[ty + 8 * i][tx] = W[(size_t)(k0 + ty + 8 * i) * N + n0 + tx];
    __syncthreads();
#pragma unroll
    for (int i = 0; i < 4; i++)
        WT[(size_t)(n0 + ty + 8 * i) * K + k0 + tx] = __float2half_rn(tbuf[tx][ty + 8 * i]);
}

__global__ void x_to_half(const float4* __restrict__ in, uint4* __restrict__ out, int n8)
{
    int i = blockIdx.x * blockDim.x + threadIdx.x;
    if (i < n8) {
        float4 v0 = in[2 * i], v1 = in[2 * i + 1];
        __half2 o[4];
        o[0] = __floats2half2_rn(v0.x, v0.y);
        o[1] = __floats2half2_rn(v0.z, v0.w);
        o[2] = __floats2half2_rn(v1.x, v1.y);
        o[3] = __floats2half2_rn(v1.z, v1.w);
        out[i] = *reinterpret_cast<uint4*>(o);
    }
}

// ---------------------------------------------------------------------------
// fp16 flash-style window attention, smem-diet edition (~14.1KB/block):
// SVr staging eliminated (V rows LDG'd into registers, stored transposed),
// SVt stride 72 -> 56 halfs.
__global__ void __launch_bounds__(32)
attn_h_kernel(const float* __restrict__ bias_table)
{
    const int head = blockIdx.x % HEADS;
    const int win  = blockIdx.x / HEADS;
    const int lane = threadIdx.x;
    const int g = lane >> 2, t = lane & 3;

    __shared__ __half SQ[64 * 40];   // 5120 B
    __shared__ __half SK[56 * 40];   // 4480 B
    __shared__ __half SVt[32 * 56];  // 3584 B  [dim][token], stride 56 halfs
    __shared__ float  Bb[224];       //  896 B  bias, +-13 guard pad

    for (int i = lane; i < 224; i += 32) Bb[i] = 0.f;
    __syncwarp();
    for (int i = lane; i < 169; i += 32) Bb[13 + i] = __ldg(&bias_table[i * HEADS + head]);

    // zero SVt (pad tokens MUST be 0: P x garbage = NaN hazard in PV)
    {
        const uint4 z = make_uint4(0, 0, 0, 0);
        uint4* v4 = reinterpret_cast<uint4*>(SVt);
        for (int i = lane; i < 32 * 56 * 2 / 16; i += 32) v4[i] = z;
    }

    // Q,K staged via cp.async from contiguous slabs
    const size_t mb = (size_t)win * NTOK;
    const __half* qs = g_qkv + ((size_t)(0 * HEADS + head) * M_TOTAL + mb) * 32;
    const __half* ks = g_qkv + ((size_t)(1 * HEADS + head) * M_TOTAL + mb) * 32;
    const __half* vs = g_qkv + ((size_t)(2 * HEADS + head) * M_TOTAL + mb) * 32;
    const uint32_t sq = smem_u32(SQ), sk = smem_u32(SK);
    for (int i = lane; i < NTOK * 4; i += 32) {
        int row = i >> 2, seg = i & 3;
        uint32_t so = (uint32_t)row * 80 + seg * 16;
        CP16(sq + so, qs + (size_t)row * 32 + seg * 8);
        CP16(sk + so, ks + (size_t)row * 32 + seg * 8);
    }
    CP_COMMIT();

    // V: coalesced LDG into registers, store transposed into SVt
    __syncwarp();   // SVt zeroing complete before partial overwrite
    for (int rr = lane; rr < NTOK; rr += 32) {
        const uint4* p = reinterpret_cast<const uint4*>(vs + (size_t)rr * 32);
        uint4 vbuf[4] = { p[0], p[1], p[2], p[3] };
        const __half* hv = reinterpret_cast<const __half*>(vbuf);
#pragma unroll
        for (int d = 0; d < 32; d++)
            SVt[d * 56 + rr] = hv[d];
    }
    CP_WAIT0();
    __syncwarp();

    // ---- QK^T ----
    float c[4][7][4];
#pragma unroll
    for (int it = 0; it < 4; it++)
#pragma unroll
        for (int jt = 0; jt < 7; jt++)
#pragma unroll
            for (int q = 0; q < 4; q++) c[it][jt][q] = 0.f;

#pragma unroll
    for (int kt = 0; kt < 2; kt++) {
        const int ko = kt * 16;
        uint32_t a[4][4];
#pragma unroll
        for (int it = 0; it < 4; it++) {
            a[it][0] = *reinterpret_cast<const uint32_t*>(&SQ[(it * 16 + g)     * 40 + ko + 2 * t]);
            a[it][1] = *reinterpret_cast<const uint32_t*>(&SQ[(it * 16 + g + 8) * 40 + ko + 2 * t]);
            a[it][2] = *reinterpret_cast<const uint32_t*>(&SQ[(it * 16 + g)     * 40 + ko + 8 + 2 * t]);
            a[it][3] = *reinterpret_cast<const uint32_t*>(&SQ[(it * 16 + g + 8) * 40 + ko + 8 + 2 * t]);
        }
#pragma unroll
        for (int jt = 0; jt < 7; jt++) {
            uint32_t b0 = *reinterpret_cast<const uint32_t*>(&SK[(jt * 8 + g) * 40 + ko + 2 * t]);
            uint32_t b1 = *reinterpret_cast<const uint32_t*>(&SK[(jt * 8 + g) * 40 + ko + 8 + 2 * t]);
#pragma unroll
            for (int it = 0; it < 4; it++)
                MMA_F16(c[it][jt], a[it][0], a[it][1], a[it][2], a[it][3], b0, b1);
        }
    }

    // ---- masked bias add + softmax ----
    const float scale = 0.17677669529663687f;
    int  pi[8];  bool rok[8];
#pragma unroll
    for (int s = 0; s < 8; s++) {
        int tok = (s >> 1) * 16 + g + 8 * (s & 1);
        rok[s] = tok < NTOK;
        int ri = tok / 7, ci = tok - ri * 7;
        pi[s] = ri * 13 + ci + 97;
    }
    int  pj[14]; bool cok[14];
#pragma unroll
    for (int u = 0; u < 14; u++) {
        int jc = (u >> 1) * 8 + 2 * t + (u & 1);
        cok[u] = jc < NTOK;
        int rj = jc / 7, cj = jc - rj * 7;
        pj[u] = rj * 13 + cj;
    }
#pragma unroll
    for (int it = 0; it < 4; it++)
#pragma unroll
        for (int jt = 0; jt < 7; jt++)
#pragma unroll
            for (int q = 0; q < 4; q++) {
                int s = it * 2 + (q >> 1), u = jt * 2 + (q & 1);
                float sc = c[it][jt][q] * scale + Bb[pi[s] - pj[u]];
                c[it][jt][q] = (rok[s] && cok[u]) ? sc : -1e9f;
            }

#pragma unroll
    for (int s = 0; s < 8; s++) {
        const int it = s >> 1, h = s & 1;
        float m = -1e9f;
#pragma unroll
        for (int jt = 0; jt < 7; jt++) {
            m = fmaxf(m, c[it][jt][h * 2]);
            m = fmaxf(m, c[it][jt][h * 2 + 1]);
        }
        m = fmaxf(m, __shfl_xor_sync(0xffffffffu, m, 1));
        m = fmaxf(m, __shfl_xor_sync(0xffffffffu, m, 2));
        float sum = 0.f;
#pragma unroll
        for (int jt = 0; jt < 7; jt++) {
            float p0 = __expf(c[it][jt][h * 2]     - m);
            float p1 = __expf(c[it][jt][h * 2 + 1] - m);
            c[it][jt][h * 2] = p0; c[it][jt][h * 2 + 1] = p1;
            sum += p0 + p1;
        }
        sum += __shfl_xor_sync(0xffffffffu, sum, 1);
        sum += __shfl_xor_sync(0xffffffffu, sum, 2);
        const float inv = 1.0f / sum;
#pragma unroll
        for (int jt = 0; jt < 7; jt++) {
            c[it][jt][h * 2]     *= inv;
            c[it][jt][h * 2 + 1] *= inv;
        }
    }

    // ---- P: accumulators -> fp16 A-fragments in registers ----
    uint32_t pa[4][4][4];
#pragma unroll
    for (int it = 0; it < 4; it++)
#pragma unroll
        for (int kt = 0; kt < 4; kt++) {
            const int jt0 = 2 * kt, jt1 = 2 * kt + 1;
            __half2 h0 = __floats2half2_rn(c[it][jt0][0], c[it][jt0][1]);
            __half2 h1 = __floats2half2_rn(c[it][jt0][2], c[it][jt0][3]);
            pa[it][kt][0] = *reinterpret_cast<uint32_t*>(&h0);
            pa[it][kt][1] = *reinterpret_cast<uint32_t*>(&h1);
            if (jt1 < 7) {
                __half2 h2 = __floats2half2_rn(c[it][jt1][0], c[it][jt1][1]);
                __half2 h3 = __floats2half2_rn(c[it][jt1][2], c[it][jt1][3]);
                pa[it][kt][2] = *reinterpret_cast<uint32_t*>(&h2);
                pa[it][kt][3] = *reinterpret_cast<uint32_t*>(&h3);
            } else {
                pa[it][kt][2] = 0u;
                pa[it][kt][3] = 0u;
            }
        }

    // ---- PV ----
    float d[4][4][4];
#pragma unroll
    for (int it = 0; it < 4; it++)
#pragma unroll
        for (int nt = 0; nt < 4; nt++)
#pragma unroll
            for (int q = 0; q < 4; q++) d[it][nt][q] = 0.f;

#pragma unroll
    for (int kt = 0; kt < 4; kt++) {
        const int ko = kt * 16;
        uint32_t b[4][2];
#pragma unroll
        for (int nt = 0; nt < 4; nt++) {
            b[nt][0] = *reinterpret_cast<const uint32_t*>(&SVt[(nt * 8 + g) * 56 + ko + 2 * t]);
            b[nt][1] = *reinterpret_cast<const uint32_t*>(&SVt[(nt * 8 + g) * 56 + ko + 8 + 2 * t]);
        }
#pragma unroll
        for (int it = 0; it < 4; it++)
#pragma unroll
            for (int nt = 0; nt < 4; nt++)
                MMA_F16(d[it][nt], pa[it][kt][0], pa[it][kt][1], pa[it][kt][2], pa[it][kt][3],
                        b[nt][0], b[nt][1]);
    }

    // ---- store half2 (proj GEMM A operand, natural order) ----
    __half* obase = g_attn + (size_t)(win * NTOK) * N_PROJ + head * 32;
#pragma unroll
    for (int it = 0; it < 4; it++)
#pragma unroll
        for (int qq = 0; qq < 2; qq++) {
            int tok = it * 16 + g + 8 * qq;
            if (tok < NTOK) {
                __half* orow = obase + (size_t)tok * N_PROJ;
#pragma unroll
                for (int nt = 0; nt < 4; nt++) {
                    __half2 hv = __floats2half2_rn(d[it][nt][2 * qq], d[it][nt][2 * qq + 1]);
                    *reinterpret_cast<__half2*>(&orow[nt * 8 + 2 * t]) = hv;
                }
            }
        }
}

// ---------------------------------------------------------------------------
extern "C" void kernel_launch(void* const* d_in, const int* in_sizes, int n_in,
                              void* d_out, int out_size)
{
    const float* x          = (const float*)d_in[0];
    const float* qkv_w      = (const float*)d_in[1];
    const float* qkv_b      = (const float*)d_in[2];
    const float* proj_w     = (const float*)d_in[3];
    const float* proj_b     = (const float*)d_in[4];
    const float* bias_table = (const float*)d_in[5];
    float* out = (float*)d_out;

    __half *qkv_p, *attn_p, *xh_p, *wtq_p, *wtp_p;
    cudaGetSymbolAddress((void**)&qkv_p,  g_qkv);
    cudaGetSymbolAddress((void**)&attn_p, g_attn);
    cudaGetSymbolAddress((void**)&xh_p,   g_xh);
    cudaGetSymbolAddress((void**)&wtq_p,  g_wtq);
    cudaGetSymbolAddress((void**)&wtp_p,  g_wtp);

    cudaFuncSetAttribute((const void*)gemm_h<N_QKV, true, false, true, __half>,
                         cudaFuncAttributeMaxDynamicSharedMemorySize, SMEM_BYTES);
    cudaFuncSetAttribute((const void*)gemm_h<N_PROJ, false, true, false, float>,
                         cudaFuncAttributeMaxDynamicSharedMemorySize, SMEM_BYTES);

    // 0) preprocessing
    {
        int n8 = M_TOTAL * KDIM / 8;
        x_to_half<<<(n8 + 255) / 256, 256>>>((const float4*)x, (uint4*)xh_p, n8);
        transpose_half<<<dim3(N_QKV / 32, KDIM / 32), dim3(32, 8)>>>(qkv_w, wtq_p, KDIM, N_QKV);
        transpose_half<<<dim3(N_PROJ / 32, KDIM / 32), dim3(32, 8)>>>(proj_w, wtp_p, KDIM, N_PROJ);
    }
    // 1) QKV GEMM (fp16 mma + ldmatrix, fused gather, head-major slab output)
    gemm_h<N_QKV, true, false, true, __half><<<dim3(N_QKV / BN, M_TOTAL / BM), 256, SMEM_BYTES>>>(
        xh_p, wtq_p, qkv_b, qkv_p);
    // 2) fp16 flash-style window attention (smem diet: ~14.1KB/block)
    attn_h_kernel<<<NWIN * HEADS, 32>>>(bias_table);
    // 3) proj GEMM (fp16 mma + ldmatrix, fused inverse roll/window scatter)
    gemm_h<N_PROJ, false, true, false, float><<<dim3(N_PROJ / BN, M_TOTAL / BM), 256, SMEM_BYTES>>>(
        attn_p, wtp_p, proj_b, out);
}